// round 1
// baseline (speedup 1.0000x reference)
#include <cuda_runtime.h>
#include <cstdint>

#define D       128
#define NMAX    50000
#define EMAX    800000
#define LN_EPS  1e-5f

// ---------------- scratch (no allocations allowed) ----------------
__device__ float g_agg[(size_t)NMAX * D];   // 25.6 MB
__device__ float g_cnt[NMAX];
__device__ float g_h1 [(size_t)NMAX * D];   // layer-1 output

// ---------------- zero kernel ----------------
__global__ void zero_kernel(float* __restrict__ p, int n) {
    int i = blockIdx.x * blockDim.x + threadIdx.x;
    int stride = gridDim.x * blockDim.x;
    for (; i < n; i += stride) p[i] = 0.0f;
}

// ---------------- scatter: one warp per edge ----------------
// agg[dst] += h[src] (512B row, float4 per lane, vectorized red)
// cnt[dst] += 1 (layer 1 only)
__global__ void scatter_kernel(const float* __restrict__ h,
                               const int*   __restrict__ src,
                               const int*   __restrict__ dst,
                               float* __restrict__ agg,
                               float* __restrict__ cnt,
                               int nE, int do_cnt)
{
    int gw   = (blockIdx.x * blockDim.x + threadIdx.x) >> 5;
    int lane = threadIdx.x & 31;
    if (gw >= nE) return;
    int s = 0, d = 0;
    if (lane == 0) { s = __ldg(&src[gw]); d = __ldg(&dst[gw]); }
    s = __shfl_sync(0xffffffffu, s, 0);
    d = __shfl_sync(0xffffffffu, d, 0);

    float4 v = ((const float4*)(h + (size_t)s * D))[lane];
    float* a = agg + (size_t)d * D + lane * 4;
    asm volatile("red.global.add.v4.f32 [%0], {%1,%2,%3,%4};"
                 :: "l"(a), "f"(v.x), "f"(v.y), "f"(v.z), "f"(v.w) : "memory");
    if (do_cnt && lane == 0) {
        asm volatile("red.global.add.f32 [%0], %1;"
                     :: "l"(cnt + d), "f"(1.0f) : "memory");
    }
}

// ---------------- fused SAGE layer: [mean||h] @ [Wl;Wr] + b -> LN -> ReLU ----
// 256 threads, tile = 32 rows x 128 cols, 4x4 register micro-tile per thread.
// smem: Wsm [256][128] (128 KB) + Asm [32][260] (33 KB)
#define A_STRIDE 260
#define SMEM_BYTES ((256 * 128 + 32 * A_STRIDE) * (int)sizeof(float))

__global__ void __launch_bounds__(256, 1)
layer_kernel(const float* __restrict__ h,
             const float* __restrict__ agg,
             const float* __restrict__ cnt,
             const float* __restrict__ Wl,
             const float* __restrict__ Wr,
             const float* __restrict__ b,
             const float* __restrict__ g,
             const float* __restrict__ be,
             float* __restrict__ out, int nN)
{
    extern __shared__ float smem[];
    float* Wsm = smem;                 // [256][128] row-major
    float* Asm = smem + 256 * 128;     // [32][A_STRIDE]

    const int tid  = threadIdx.x;
    const int row0 = blockIdx.x * 32;

    // ---- load [Wl;Wr] into smem (float4, coalesced, conflict-free) ----
    for (int idx = tid; idx < 256 * 32; idx += 256) {
        int k = idx >> 5, q = idx & 31;
        float4 v = (k < 128) ? ((const float4*)Wl)[k * 32 + q]
                             : ((const float4*)Wr)[(k - 128) * 32 + q];
        ((float4*)Wsm)[k * 32 + q] = v;
    }
    // ---- load A tile: cols 0..127 = agg/max(cnt,1), 128..255 = h ----
    for (int idx = tid; idx < 32 * 64; idx += 256) {
        int r = idx >> 6, q = idx & 63;
        int row = row0 + r;
        float4 v = make_float4(0.f, 0.f, 0.f, 0.f);
        if (row < nN) {
            if (q < 32) {
                float ic = 1.0f / fmaxf(__ldg(&cnt[row]), 1.0f);
                float4 t = ((const float4*)(agg + (size_t)row * D))[q];
                v.x = t.x * ic; v.y = t.y * ic; v.z = t.z * ic; v.w = t.w * ic;
            } else {
                v = ((const float4*)(h + (size_t)row * D))[q - 32];
            }
        }
        *(float4*)(Asm + r * A_STRIDE + q * 4) = v;
    }
    __syncthreads();

    const int tc = tid & 31;   // column group: cols tc*4 .. tc*4+3
    const int tr = tid >> 5;   // warp id: rows tr*4 .. tr*4+3 (LN is warp-local)
    const float* A0 = Asm + (tr * 4) * A_STRIDE;

    float acc[4][4];
#pragma unroll
    for (int i = 0; i < 4; i++)
#pragma unroll
        for (int j = 0; j < 4; j++) acc[i][j] = 0.0f;

#pragma unroll 4
    for (int kk = 0; kk < 256; kk += 4) {
        float4 a0 = *(const float4*)(A0 + 0 * A_STRIDE + kk);
        float4 a1 = *(const float4*)(A0 + 1 * A_STRIDE + kk);
        float4 a2 = *(const float4*)(A0 + 2 * A_STRIDE + kk);
        float4 a3 = *(const float4*)(A0 + 3 * A_STRIDE + kk);
        const float* p0 = (const float*)&a0;
        const float* p1 = (const float*)&a1;
        const float* p2 = (const float*)&a2;
        const float* p3 = (const float*)&a3;
#pragma unroll
        for (int i = 0; i < 4; i++) {
            float4 w = *(const float4*)(Wsm + (kk + i) * 128 + tc * 4);
            float v0 = p0[i], v1 = p1[i], v2 = p2[i], v3 = p3[i];
            acc[0][0] += v0 * w.x; acc[0][1] += v0 * w.y; acc[0][2] += v0 * w.z; acc[0][3] += v0 * w.w;
            acc[1][0] += v1 * w.x; acc[1][1] += v1 * w.y; acc[1][2] += v1 * w.z; acc[1][3] += v1 * w.w;
            acc[2][0] += v2 * w.x; acc[2][1] += v2 * w.y; acc[2][2] += v2 * w.z; acc[2][3] += v2 * w.w;
            acc[3][0] += v3 * w.x; acc[3][1] += v3 * w.y; acc[3][2] += v3 * w.z; acc[3][3] += v3 * w.w;
        }
    }

    // ---- epilogue: +bias, LayerNorm (warp-local per row), ReLU, store ----
    float4 bb = ((const float4*)b )[tc];
    float4 gg = ((const float4*)g )[tc];
    float4 ee = ((const float4*)be)[tc];
#pragma unroll
    for (int i = 0; i < 4; i++) {
        float4 o;
        o.x = acc[i][0] + bb.x;
        o.y = acc[i][1] + bb.y;
        o.z = acc[i][2] + bb.z;
        o.w = acc[i][3] + bb.w;
        float s  = o.x + o.y + o.z + o.w;
        float sq = o.x * o.x + o.y * o.y + o.z * o.z + o.w * o.w;
#pragma unroll
        for (int off = 16; off; off >>= 1) {
            s  += __shfl_xor_sync(0xffffffffu, s,  off);
            sq += __shfl_xor_sync(0xffffffffu, sq, off);
        }
        float mu  = s * (1.0f / 128.0f);
        float var = sq * (1.0f / 128.0f) - mu * mu;
        float rs  = rsqrtf(var + LN_EPS);
        int row = row0 + tr * 4 + i;
        if (row < nN) {
            float4 r4;
            r4.x = fmaxf((o.x - mu) * rs * gg.x + ee.x, 0.0f);
            r4.y = fmaxf((o.y - mu) * rs * gg.y + ee.y, 0.0f);
            r4.z = fmaxf((o.z - mu) * rs * gg.z + ee.z, 0.0f);
            r4.w = fmaxf((o.w - mu) * rs * gg.w + ee.w, 0.0f);
            ((float4*)(out + (size_t)row * D))[tc] = r4;
        }
    }
}

// ---------------- launch ----------------
extern "C" void kernel_launch(void* const* d_in, const int* in_sizes, int n_in,
                              void* d_out, int out_size)
{
    const float* x    = (const float*)d_in[0];
    const int*   ei   = (const int*)  d_in[1];
    const float* Wl1  = (const float*)d_in[2];
    const float* Wr1  = (const float*)d_in[3];
    const float* b1   = (const float*)d_in[4];
    const float* g1   = (const float*)d_in[5];
    const float* be1  = (const float*)d_in[6];
    const float* Wl2  = (const float*)d_in[7];
    const float* Wr2  = (const float*)d_in[8];
    const float* b2   = (const float*)d_in[9];
    const float* g2   = (const float*)d_in[10];
    const float* be2  = (const float*)d_in[11];
    float* out = (float*)d_out;

    const int nN = in_sizes[0] / D;
    const int nE = in_sizes[1] / 2;
    const int* src = ei;
    const int* dst = ei + nE;

    float *agg, *cnt, *h1;
    cudaGetSymbolAddress((void**)&agg, g_agg);
    cudaGetSymbolAddress((void**)&cnt, g_cnt);
    cudaGetSymbolAddress((void**)&h1,  g_h1);

    cudaFuncSetAttribute(layer_kernel,
                         cudaFuncAttributeMaxDynamicSharedMemorySize, SMEM_BYTES);

    const int zeroBlocks = 2048;
    const int scatBlocks = (nE * 32 + 255) / 256;
    const int gemmBlocks = (nN + 31) / 32;

    // ---- layer 1 ----
    zero_kernel<<<zeroBlocks, 256>>>(agg, nN * D);
    zero_kernel<<<256, 256>>>(cnt, nN);
    scatter_kernel<<<scatBlocks, 256>>>(x, src, dst, agg, cnt, nE, 1);
    layer_kernel<<<gemmBlocks, 256, SMEM_BYTES>>>(x, agg, cnt,
                                                  Wl1, Wr1, b1, g1, be1, h1, nN);
    // ---- layer 2 (cnt reused) ----
    zero_kernel<<<zeroBlocks, 256>>>(agg, nN * D);
    scatter_kernel<<<scatBlocks, 256>>>(h1, src, dst, agg, cnt, nE, 0);
    layer_kernel<<<gemmBlocks, 256, SMEM_BYTES>>>(h1, agg, cnt,
                                                  Wl2, Wr2, b2, g2, be2, out, nN);
}

// round 2
// speedup vs baseline: 1.3598x; 1.3598x over previous
#include <cuda_runtime.h>
#include <cuda_bf16.h>
#include <cstdint>

#define D       128
#define NMAX    50000
#define EMAX    800000
#define LN_EPS  1e-5f

// ---------------- scratch (no allocations allowed) ----------------
__device__ float g_agg[(size_t)NMAX * D];           // 25.6 MB
__device__ float g_cnt[NMAX];
__device__ float g_h1 [(size_t)NMAX * D];           // layer-1 output
__device__ __nv_bfloat16 g_whi[2][128 * 256];       // W^T hi, per layer, [n][k]
__device__ __nv_bfloat16 g_wlo[2][128 * 256];       // W^T lo

// ---------------- zero kernel ----------------
__global__ void zero_kernel(float* __restrict__ p, int n) {
    int i = blockIdx.x * blockDim.x + threadIdx.x;
    int stride = gridDim.x * blockDim.x;
    for (; i < n; i += stride) p[i] = 0.0f;
}

// ---------------- weight split kernel: W^T -> bf16 hi/lo ----------------
// layer l, n in [0,128), k in [0,256): W[k][n] with k<128 -> Wl, else Wr
__global__ void wsplit_kernel(const float* __restrict__ Wl1, const float* __restrict__ Wr1,
                              const float* __restrict__ Wl2, const float* __restrict__ Wr2)
{
    int t = blockIdx.x * blockDim.x + threadIdx.x;
    if (t >= 2 * 128 * 256) return;
    int l = t >> 15;
    int n = (t >> 8) & 127;
    int k = t & 255;
    const float* Wl = l ? Wl2 : Wl1;
    const float* Wr = l ? Wr2 : Wr1;
    float w = (k < 128) ? Wl[k * D + n] : Wr[(k - 128) * D + n];
    __nv_bfloat16 hi = __float2bfloat16(w);
    __nv_bfloat16 lo = __float2bfloat16(w - __bfloat162float(hi));
    g_whi[l][n * 256 + k] = hi;
    g_wlo[l][n * 256 + k] = lo;
}

// ---------------- scatter: one warp per edge ----------------
__global__ void scatter_kernel(const float* __restrict__ h,
                               const int*   __restrict__ src,
                               const int*   __restrict__ dst,
                               float* __restrict__ agg,
                               float* __restrict__ cnt,
                               int nE, int do_cnt)
{
    int gw   = (blockIdx.x * blockDim.x + threadIdx.x) >> 5;
    int lane = threadIdx.x & 31;
    if (gw >= nE) return;
    int s = 0, d = 0;
    if (lane == 0) { s = __ldg(&src[gw]); d = __ldg(&dst[gw]); }
    s = __shfl_sync(0xffffffffu, s, 0);
    d = __shfl_sync(0xffffffffu, d, 0);

    float4 v = ((const float4*)(h + (size_t)s * D))[lane];
    float* a = agg + (size_t)d * D + lane * 4;
    asm volatile("red.global.add.v4.f32 [%0], {%1,%2,%3,%4};"
                 :: "l"(a), "f"(v.x), "f"(v.y), "f"(v.z), "f"(v.w) : "memory");
    if (do_cnt && lane == 0) {
        asm volatile("red.global.add.f32 [%0], %1;"
                     :: "l"(cnt + d), "f"(1.0f) : "memory");
    }
}

// ---------------- fused SAGE layer (tensor core, bf16x3) ----------------
// Block: 256 threads = 8 warps (4 row-groups x 2 col-groups).
// Block tile: 128 rows x 128 cols, K=256 in two 128-chunks.
// smem: Whi[128n][264k] + Wlo  (135168 B) + Ahi[128r][136k] + Alo (69632 B)
#define WS 264
#define AS 136
#define CS 132
#define W_HI_OFF 0
#define W_LO_OFF 67584
#define A_HI_OFF 135168
#define A_LO_OFF 169984
#define SMEM_TOTAL 204800

#define MMA16816(d, a, b0, b1)                                              \
    asm volatile("mma.sync.aligned.m16n8k16.row.col.f32.bf16.bf16.f32 "     \
                 "{%0,%1,%2,%3}, {%4,%5,%6,%7}, {%8,%9}, {%0,%1,%2,%3};"    \
                 : "+f"(d[0]), "+f"(d[1]), "+f"(d[2]), "+f"(d[3])           \
                 : "r"(a[0]), "r"(a[1]), "r"(a[2]), "r"(a[3]),              \
                   "r"(b0), "r"(b1))

__global__ void __launch_bounds__(256, 1)
layer_kernel(const float* __restrict__ h,
             const float* __restrict__ agg,
             const float* __restrict__ cnt,
             const __nv_bfloat16* __restrict__ whi,
             const __nv_bfloat16* __restrict__ wlo,
             const float* __restrict__ b,
             const float* __restrict__ g,
             const float* __restrict__ be,
             float* __restrict__ out, int nN)
{
    extern __shared__ char smem_raw[];
    __nv_bfloat16* Whi_s = (__nv_bfloat16*)(smem_raw + W_HI_OFF);
    __nv_bfloat16* Wlo_s = (__nv_bfloat16*)(smem_raw + W_LO_OFF);
    __nv_bfloat16* Ahi_s = (__nv_bfloat16*)(smem_raw + A_HI_OFF);
    __nv_bfloat16* Alo_s = (__nv_bfloat16*)(smem_raw + A_LO_OFF);

    const int tid  = threadIdx.x;
    const int lane = tid & 31;
    const int wid  = tid >> 5;
    const int gq   = lane >> 2;     // 0..7
    const int cq   = lane & 3;      // 0..3
    const int row0 = blockIdx.x * 128;
    const int row0w = (wid >> 1) * 32;   // warp row base within tile
    const int col0w = (wid & 1) * 64;    // warp col base within tile

    // ---- load W^T hi/lo into smem (uint4, coalesced, conflict-free) ----
    for (int it = tid; it < 128 * 32; it += 256) {
        int n  = it >> 5;
        int k8 = (it & 31) * 8;
        uint4 vh = ((const uint4*)(whi + n * 256))[it & 31];
        uint4 vl = ((const uint4*)(wlo + n * 256))[it & 31];
        *(uint4*)(Whi_s + n * WS + k8) = vh;
        *(uint4*)(Wlo_s + n * WS + k8) = vl;
    }

    float acc[2][8][4];
#pragma unroll
    for (int i = 0; i < 2; i++)
#pragma unroll
        for (int j = 0; j < 8; j++)
#pragma unroll
            for (int q = 0; q < 4; q++) acc[i][j][q] = 0.0f;

    for (int chunk = 0; chunk < 2; chunk++) {
        // ---- fill A chunk (fp32 -> bf16 hi/lo), chunk0 = mean(agg), chunk1 = h
        for (int it = tid; it < 128 * 32; it += 256) {
            int r = it >> 5, q = it & 31;
            int row = row0 + r;
            float4 v = make_float4(0.f, 0.f, 0.f, 0.f);
            if (row < nN) {
                if (chunk == 0) {
                    float ic = 1.0f / fmaxf(__ldg(&cnt[row]), 1.0f);
                    float4 t = ((const float4*)(agg + (size_t)row * D))[q];
                    v.x = t.x * ic; v.y = t.y * ic; v.z = t.z * ic; v.w = t.w * ic;
                } else {
                    v = ((const float4*)(h + (size_t)row * D))[q];
                }
            }
            __nv_bfloat16 hx = __float2bfloat16(v.x), lx = __float2bfloat16(v.x - __bfloat162float(hx));
            __nv_bfloat16 hy = __float2bfloat16(v.y), ly = __float2bfloat16(v.y - __bfloat162float(hy));
            __nv_bfloat16 hz = __float2bfloat16(v.z), lz = __float2bfloat16(v.z - __bfloat162float(hz));
            __nv_bfloat16 hw = __float2bfloat16(v.w), lw = __float2bfloat16(v.w - __bfloat162float(hw));
            __nv_bfloat16* ph = Ahi_s + r * AS + q * 4;
            __nv_bfloat16* pl = Alo_s + r * AS + q * 4;
            *(__nv_bfloat162*)(ph)     = __nv_bfloat162(hx, hy);
            *(__nv_bfloat162*)(ph + 2) = __nv_bfloat162(hz, hw);
            *(__nv_bfloat162*)(pl)     = __nv_bfloat162(lx, ly);
            *(__nv_bfloat162*)(pl + 2) = __nv_bfloat162(lz, lw);
        }
        __syncthreads();

        const int kbase = chunk * 128;
#pragma unroll
        for (int ks = 0; ks < 128; ks += 16) {
            uint ah[2][4], al[2][4];
            const __nv_bfloat16* pa = Ahi_s + (row0w + gq) * AS + ks + 2 * cq;
            const __nv_bfloat16* pl = Alo_s + (row0w + gq) * AS + ks + 2 * cq;
#pragma unroll
            for (int i = 0; i < 2; i++) {
                ah[i][0] = *(const unsigned*)(pa + (i * 16) * AS);
                ah[i][1] = *(const unsigned*)(pa + (i * 16 + 8) * AS);
                ah[i][2] = *(const unsigned*)(pa + (i * 16) * AS + 8);
                ah[i][3] = *(const unsigned*)(pa + (i * 16 + 8) * AS + 8);
                al[i][0] = *(const unsigned*)(pl + (i * 16) * AS);
                al[i][1] = *(const unsigned*)(pl + (i * 16 + 8) * AS);
                al[i][2] = *(const unsigned*)(pl + (i * 16) * AS + 8);
                al[i][3] = *(const unsigned*)(pl + (i * 16 + 8) * AS + 8);
            }
#pragma unroll
            for (int j = 0; j < 8; j++) {
                const __nv_bfloat16* pbh = Whi_s + (col0w + j * 8 + gq) * WS + kbase + ks + 2 * cq;
                const __nv_bfloat16* pbl = Wlo_s + (col0w + j * 8 + gq) * WS + kbase + ks + 2 * cq;
                unsigned bh0 = *(const unsigned*)(pbh);
                unsigned bh1 = *(const unsigned*)(pbh + 8);
                unsigned bl0 = *(const unsigned*)(pbl);
                unsigned bl1 = *(const unsigned*)(pbl + 8);
                MMA16816(acc[0][j], ah[0], bh0, bh1);
                MMA16816(acc[1][j], ah[1], bh0, bh1);
                MMA16816(acc[0][j], ah[0], bl0, bl1);
                MMA16816(acc[1][j], ah[1], bl0, bl1);
                MMA16816(acc[0][j], al[0], bh0, bh1);
                MMA16816(acc[1][j], al[1], bh0, bh1);
            }
        }
        __syncthreads();
    }

    // ---- epilogue: dump accums to smem (reuse A region), then LN+ReLU ----
    float* Csm = (float*)(smem_raw + A_HI_OFF);   // [128][CS]
#pragma unroll
    for (int i = 0; i < 2; i++)
#pragma unroll
        for (int j = 0; j < 8; j++) {
            int r = row0w + i * 16 + gq;
            float* p = Csm + r * CS + col0w + j * 8 + 2 * cq;
            p[0] = acc[i][j][0];
            p[1] = acc[i][j][1];
            (p + 8 * CS)[0] = acc[i][j][2];
            (p + 8 * CS)[1] = acc[i][j][3];
        }
    __syncthreads();

    float4 bb = ((const float4*)b )[lane];
    float4 gg = ((const float4*)g )[lane];
    float4 ee = ((const float4*)be)[lane];
#pragma unroll 4
    for (int rr = 0; rr < 16; rr++) {
        int r = wid * 16 + rr;
        int row = row0 + r;
        float4 o = *(float4*)(Csm + r * CS + lane * 4);
        o.x += bb.x; o.y += bb.y; o.z += bb.z; o.w += bb.w;
        float s  = o.x + o.y + o.z + o.w;
        float sq = o.x * o.x + o.y * o.y + o.z * o.z + o.w * o.w;
#pragma unroll
        for (int off = 16; off; off >>= 1) {
            s  += __shfl_xor_sync(0xffffffffu, s,  off);
            sq += __shfl_xor_sync(0xffffffffu, sq, off);
        }
        float mu  = s * (1.0f / 128.0f);
        float var = sq * (1.0f / 128.0f) - mu * mu;
        float rs  = rsqrtf(var + LN_EPS);
        if (row < nN) {
            float4 r4;
            r4.x = fmaxf((o.x - mu) * rs * gg.x + ee.x, 0.0f);
            r4.y = fmaxf((o.y - mu) * rs * gg.y + ee.y, 0.0f);
            r4.z = fmaxf((o.z - mu) * rs * gg.z + ee.z, 0.0f);
            r4.w = fmaxf((o.w - mu) * rs * gg.w + ee.w, 0.0f);
            ((float4*)(out + (size_t)row * D))[lane] = r4;
        }
    }
}

// ---------------- launch ----------------
extern "C" void kernel_launch(void* const* d_in, const int* in_sizes, int n_in,
                              void* d_out, int out_size)
{
    const float* x    = (const float*)d_in[0];
    const int*   ei   = (const int*)  d_in[1];
    const float* Wl1  = (const float*)d_in[2];
    const float* Wr1  = (const float*)d_in[3];
    const float* b1   = (const float*)d_in[4];
    const float* g1   = (const float*)d_in[5];
    const float* be1  = (const float*)d_in[6];
    const float* Wl2  = (const float*)d_in[7];
    const float* Wr2  = (const float*)d_in[8];
    const float* b2   = (const float*)d_in[9];
    const float* g2   = (const float*)d_in[10];
    const float* be2  = (const float*)d_in[11];
    float* out = (float*)d_out;

    const int nN = in_sizes[0] / D;
    const int nE = in_sizes[1] / 2;
    const int* src = ei;
    const int* dst = ei + nE;

    float *agg, *cnt, *h1;
    __nv_bfloat16 *whi, *wlo;
    cudaGetSymbolAddress((void**)&agg, g_agg);
    cudaGetSymbolAddress((void**)&cnt, g_cnt);
    cudaGetSymbolAddress((void**)&h1,  g_h1);
    cudaGetSymbolAddress((void**)&whi, g_whi);
    cudaGetSymbolAddress((void**)&wlo, g_wlo);

    cudaFuncSetAttribute(layer_kernel,
                         cudaFuncAttributeMaxDynamicSharedMemorySize, SMEM_TOTAL);

    const int zeroBlocks = 2048;
    const int scatBlocks = (nE * 32 + 255) / 256;
    const int gemmBlocks = (nN + 127) / 128;

    // ---- weight preprocessing (both layers) ----
    wsplit_kernel<<<(2 * 128 * 256 + 255) / 256, 256>>>(Wl1, Wr1, Wl2, Wr2);

    // ---- layer 1 ----
    zero_kernel<<<zeroBlocks, 256>>>(agg, nN * D);
    zero_kernel<<<256, 256>>>(cnt, nN);
    scatter_kernel<<<scatBlocks, 256>>>(x, src, dst, agg, cnt, nE, 1);
    layer_kernel<<<gemmBlocks, 256, SMEM_TOTAL>>>(x, agg, cnt,
                                                  whi, wlo,
                                                  b1, g1, be1, h1, nN);
    // ---- layer 2 (cnt reused) ----
    zero_kernel<<<zeroBlocks, 256>>>(agg, nN * D);
    scatter_kernel<<<scatBlocks, 256>>>(h1, src, dst, agg, cnt, nE, 0);
    layer_kernel<<<gemmBlocks, 256, SMEM_TOTAL>>>(h1, agg, cnt,
                                                  whi + 128 * 256, wlo + 128 * 256,
                                                  b2, g2, be2, out, nN);
}